// round 8
// baseline (speedup 1.0000x reference)
#include <cuda_runtime.h>

// z_hat [B,T,D] f32, P [B,T] f32, lengths [B] i32 -> out [B,T,D] f32
#define BB 4
#define TT 4096
#define DD 512
#define CC 256              // chunks along T
#define LL 16               // chunk length
#define D4 128              // float4 lanes per row (DD/4)
#define NCHUNK (BB*CC)      // 1024 chunks, flattened idx = b*CC + c
#define NPAIR 512           // blocks in k1/k3 (each owns chunks j and 1023-j)

// Scratch (__device__ globals; allocation-free rule). idx = b*CC + c.
__device__ float g_Bsum[NCHUNK * DD];
__device__ float g_A[NCHUNK];
__device__ float g_Zinit[NCHUNK * DD];

// ---------------------------------------------------------------------------
// K1: per-chunk weighted reduction. 256-thread blocks, 2 halves; half h owns
// chunk f = j (h=0) or f = NCHUNK-1-j (h=1)  -> antithetic masked/active mix.
// Loads forced front-batched (8-deep) via compiler barrier; 4 accumulators.
// ---------------------------------------------------------------------------
__global__ void __launch_bounds__(256, 3) k1_chunk_summary(
    const float* __restrict__ z, const float* __restrict__ P,
    const int* __restrict__ lengths)
{
    const int j = blockIdx.x;
    const int tid = threadIdx.x;
    const int lane = tid & 127;      // float4 lane over D
    const int h = tid >> 7;          // which chunk of the pair

    const int f = h ? (NCHUNK - 1 - j) : j;
    const int b = f >> 8;            // f / CC
    const int c = f & (CC - 1);
    const int len = lengths[b];
    const int t0 = c * LL;
    if (t0 >= len) return;           // masked chunk: state never consumed

    // suffix weights in registers: w[k] = pe[k] * prod_{m>k} q[m], A = prod q
    float w[LL];
    float r = 1.0f;
#pragma unroll
    for (int k = LL - 1; k >= 0; --k) {
        float p = __ldg(&P[b * TT + t0 + k]);       // warp-uniform broadcast
        p = fminf(fmaxf(p, 0.0f), 1.0f - 1e-6f);
        w[k] = fmaxf(p, 1e-6f) * r;
        r *= (1.0f - p);
    }

    const float4* __restrict__ zp =
        (const float4*)(z + ((size_t)b * TT + t0) * DD);

    float4 a0 = make_float4(0.f, 0.f, 0.f, 0.f);
    float4 a1 = make_float4(0.f, 0.f, 0.f, 0.f);
    float4 a2 = make_float4(0.f, 0.f, 0.f, 0.f);
    float4 a3 = make_float4(0.f, 0.f, 0.f, 0.f);

#pragma unroll
    for (int kb = 0; kb < LL; kb += 8) {
        float4 x0 = zp[(size_t)(kb + 0) * D4 + lane];
        float4 x1 = zp[(size_t)(kb + 1) * D4 + lane];
        float4 x2 = zp[(size_t)(kb + 2) * D4 + lane];
        float4 x3 = zp[(size_t)(kb + 3) * D4 + lane];
        float4 x4 = zp[(size_t)(kb + 4) * D4 + lane];
        float4 x5 = zp[(size_t)(kb + 5) * D4 + lane];
        float4 x6 = zp[(size_t)(kb + 6) * D4 + lane];
        float4 x7 = zp[(size_t)(kb + 7) * D4 + lane];
        asm volatile("" ::: "memory");   // keep the 8 loads front-batched
        a0.x = fmaf(w[kb+0], x0.x, a0.x); a0.y = fmaf(w[kb+0], x0.y, a0.y);
        a0.z = fmaf(w[kb+0], x0.z, a0.z); a0.w = fmaf(w[kb+0], x0.w, a0.w);
        a1.x = fmaf(w[kb+1], x1.x, a1.x); a1.y = fmaf(w[kb+1], x1.y, a1.y);
        a1.z = fmaf(w[kb+1], x1.z, a1.z); a1.w = fmaf(w[kb+1], x1.w, a1.w);
        a2.x = fmaf(w[kb+2], x2.x, a2.x); a2.y = fmaf(w[kb+2], x2.y, a2.y);
        a2.z = fmaf(w[kb+2], x2.z, a2.z); a2.w = fmaf(w[kb+2], x2.w, a2.w);
        a3.x = fmaf(w[kb+3], x3.x, a3.x); a3.y = fmaf(w[kb+3], x3.y, a3.y);
        a3.z = fmaf(w[kb+3], x3.z, a3.z); a3.w = fmaf(w[kb+3], x3.w, a3.w);
        a0.x = fmaf(w[kb+4], x4.x, a0.x); a0.y = fmaf(w[kb+4], x4.y, a0.y);
        a0.z = fmaf(w[kb+4], x4.z, a0.z); a0.w = fmaf(w[kb+4], x4.w, a0.w);
        a1.x = fmaf(w[kb+5], x5.x, a1.x); a1.y = fmaf(w[kb+5], x5.y, a1.y);
        a1.z = fmaf(w[kb+5], x5.z, a1.z); a1.w = fmaf(w[kb+5], x5.w, a1.w);
        a2.x = fmaf(w[kb+6], x6.x, a2.x); a2.y = fmaf(w[kb+6], x6.y, a2.y);
        a2.z = fmaf(w[kb+6], x6.z, a2.z); a2.w = fmaf(w[kb+6], x6.w, a2.w);
        a3.x = fmaf(w[kb+7], x7.x, a3.x); a3.y = fmaf(w[kb+7], x7.y, a3.y);
        a3.z = fmaf(w[kb+7], x7.z, a3.z); a3.w = fmaf(w[kb+7], x7.w, a3.w);
    }
    float4 acc = make_float4((a0.x + a1.x) + (a2.x + a3.x),
                             (a0.y + a1.y) + (a2.y + a3.y),
                             (a0.z + a1.z) + (a2.z + a3.z),
                             (a0.w + a1.w) + (a2.w + a3.w));
    ((float4*)g_Bsum)[(size_t)f * D4 + lane] = acc;
    if (lane == 0) g_A[f] = r;
}

// ---------------------------------------------------------------------------
// K2: parallel cross-chunk scan (Hillis-Steele over affine maps), verbatim
// from the passing R5 version. Block = (b, d4-lane), thread c owns chunk c.
// Garbage in masked chunks (c >= cmax) only flows upward -> never consumed.
// ---------------------------------------------------------------------------
__global__ void __launch_bounds__(CC) k2_scan()
{
    const int b = blockIdx.x;
    const int g = blockIdx.y;     // d4 lane 0..127
    const int c = threadIdx.x;    // chunk id 0..CC-1

    __shared__ float sA[CC];
    __shared__ float4 sB[CC];

    float a = g_A[b * CC + c];
    float4 v = ((const float4*)g_Bsum)[(size_t)(b * CC + c) * D4 + g];
    sA[c] = a; sB[c] = v;
    __syncthreads();

#pragma unroll
    for (int s = 1; s < CC; s <<= 1) {
        float pa = 1.0f;
        float4 pb = make_float4(0.f, 0.f, 0.f, 0.f);
        if (c >= s) { pa = sA[c - s]; pb = sB[c - s]; }
        __syncthreads();
        if (c >= s) {
            v.x = fmaf(a, pb.x, v.x);
            v.y = fmaf(a, pb.y, v.y);
            v.z = fmaf(a, pb.z, v.z);
            v.w = fmaf(a, pb.w, v.w);
            a *= pa;
            sA[c] = a; sB[c] = v;
        }
        __syncthreads();
    }

    float4 zo = (c == 0) ? make_float4(0.f, 0.f, 0.f, 0.f) : sB[c - 1];
    ((float4*)g_Zinit)[(size_t)(b * CC + c) * D4 + g] = zo;
}

// ---------------------------------------------------------------------------
// K3: per-chunk local scan seeded with Zinit; mask; write out. Same pairing
// and load batching as K1. Fully-masked chunks zero-fill with no loads.
// ---------------------------------------------------------------------------
__global__ void __launch_bounds__(256, 3) k3_scan_out(
    const float* __restrict__ z, const float* __restrict__ P,
    const int* __restrict__ lengths, float* __restrict__ out)
{
    const int j = blockIdx.x;
    const int tid = threadIdx.x;
    const int lane = tid & 127;
    const int h = tid >> 7;

    const int f = h ? (NCHUNK - 1 - j) : j;
    const int b = f >> 8;
    const int c = f & (CC - 1);
    const int len = lengths[b];
    const int t0 = c * LL;

    float4* __restrict__ op = (float4*)(out + ((size_t)b * TT + t0) * DD);

    if (t0 >= len) {                 // fully masked: zero-fill, no loads
        float4 zero = make_float4(0.f, 0.f, 0.f, 0.f);
#pragma unroll
        for (int k = 0; k < LL; ++k) op[(size_t)k * D4 + lane] = zero;
        return;
    }

    // carry load issued early (hides L2 latency behind P loads)
    float4 zv = ((const float4*)g_Zinit)[(size_t)f * D4 + lane];

    float pc[LL];                    // clamped P; q/pe derived at use (reg save)
#pragma unroll
    for (int k = 0; k < LL; ++k) {
        float p = __ldg(&P[b * TT + t0 + k]);
        pc[k] = fminf(fmaxf(p, 0.0f), 1.0f - 1e-6f);
    }

    const float4* __restrict__ zp =
        (const float4*)(z + ((size_t)b * TT + t0) * DD);

#pragma unroll
    for (int kb = 0; kb < LL; kb += 8) {
        float4 x0 = zp[(size_t)(kb + 0) * D4 + lane];
        float4 x1 = zp[(size_t)(kb + 1) * D4 + lane];
        float4 x2 = zp[(size_t)(kb + 2) * D4 + lane];
        float4 x3 = zp[(size_t)(kb + 3) * D4 + lane];
        float4 x4 = zp[(size_t)(kb + 4) * D4 + lane];
        float4 x5 = zp[(size_t)(kb + 5) * D4 + lane];
        float4 x6 = zp[(size_t)(kb + 6) * D4 + lane];
        float4 x7 = zp[(size_t)(kb + 7) * D4 + lane];
        asm volatile("" ::: "memory");   // keep the 8 loads front-batched
#pragma unroll
        for (int u = 0; u < 8; ++u) {
            const int kk = kb + u;
            float4 x = (u == 0) ? x0 : (u == 1) ? x1 : (u == 2) ? x2 : (u == 3) ? x3
                     : (u == 4) ? x4 : (u == 5) ? x5 : (u == 6) ? x6 : x7;
            float q = 1.0f - pc[kk];
            float pe = fmaxf(pc[kk], 1e-6f);
            zv.x = fmaf(q, zv.x, pe * x.x);
            zv.y = fmaf(q, zv.y, pe * x.y);
            zv.z = fmaf(q, zv.z, pe * x.z);
            zv.w = fmaf(q, zv.w, pe * x.w);
            float m = (t0 + kk < len) ? 1.0f : 0.0f;
            op[(size_t)kk * D4 + lane] =
                make_float4(zv.x * m, zv.y * m, zv.z * m, zv.w * m);
        }
    }
}

extern "C" void kernel_launch(void* const* d_in, const int* in_sizes, int n_in,
                              void* d_out, int out_size)
{
    const float* z = (const float*)d_in[0];
    const float* P = (const float*)d_in[1];
    const int* lengths = (const int*)d_in[2];
    float* out = (float*)d_out;

    k1_chunk_summary<<<NPAIR, 256>>>(z, P, lengths);
    dim3 gridS(BB, D4);
    k2_scan<<<gridS, CC>>>();
    k3_scan_out<<<NPAIR, 256>>>(z, P, lengths, out);
}